// round 17
// baseline (speedup 1.0000x reference)
#include <cuda_runtime.h>
#include <cuda_fp16.h>
#include <cstdint>

// Problem dims (fixed by dataset)
#define BB 4
#define TT_ 512
#define UU 128
#define DD 512
#define VV 512
#define MS (BB * TT_)    // 2048 speech rows
#define MT (BB * UU)     // 512 text rows
#define MA (MS + MT)     // 2560 combined A rows

// Scratch
__device__ float g_sp[MS * VV];   // speech @ W^T          (4 MB)
__device__ float g_tp[MT * VV];   // text @ W^T + bias     (1 MB)
__device__ __align__(16) __half g_Ah[MA * DD];   // fp16(A)
__device__ __align__(16) __half g_Wh[VV * DD];   // fp16(W * 2^9) hi
__device__ __align__(16) __half g_Wl[VV * DD];   // fp16 residual of W * 2^9

// Dependency flags (zeroed by convert block 0 each launch)
__device__ unsigned int g_sp_cnt[32];   // per 64-row speech block: target 8
__device__ unsigned int g_tp_cnt;       // text tiles done: target 64

#define WSCALE 512.0f
#define WINV   0.001953125f   // 2^-9 exact

__device__ __forceinline__ uint32_t s2u(const void* p) {
    return (uint32_t)__cvta_generic_to_shared(p);
}

#define LDSM4(r0, r1, r2, r3, addr) \
    asm volatile("ldmatrix.sync.aligned.m8n8.x4.shared.b16 {%0,%1,%2,%3}, [%4];" \
                 : "=r"(r0), "=r"(r1), "=r"(r2), "=r"(r3) : "r"(addr))
#define MMA16816F16(d, a0, a1, a2, a3, b0, b1) \
    asm volatile("mma.sync.aligned.m16n8k16.row.col.f32.f16.f16.f32 " \
                 "{%0,%1,%2,%3},{%4,%5,%6,%7},{%8,%9},{%0,%1,%2,%3};" \
                 : "+f"(d[0]), "+f"(d[1]), "+f"(d[2]), "+f"(d[3]) \
                 : "r"(a0), "r"(a1), "r"(a2), "r"(a3), "r"(b0), "r"(b1))
#define CP16(saddr, gptr) \
    asm volatile("cp.async.cg.shared.global [%0], [%1], 16;" \
                 :: "r"(saddr), "l"(gptr))
#define CP_COMMIT() asm volatile("cp.async.commit_group;")
#define CP_WAIT1()  asm volatile("cp.async.wait_group 1;")
#define CP_WAIT0()  asm volatile("cp.async.wait_group 0;")

// ---------------------------------------------------------------------------
// Kernel 0: convert + counter reset + length tail.
// A -> fp16. W -> (fp16 hi, fp16 lo) of W*2^9.
// 768 blocks x 256 threads x 8 elems = 1,572,864 elements exactly.
// ---------------------------------------------------------------------------
__global__ __launch_bounds__(256)
void convert_kernel(const float* __restrict__ speech,
                    const float* __restrict__ text,
                    const float* __restrict__ Wm,
                    const int* __restrict__ slen,
                    const int* __restrict__ tlen,
                    float* __restrict__ out)
{
    const size_t e = ((size_t)blockIdx.x * 256 + threadIdx.x) * 8;

    if (e < (size_t)MA * DD) {
        const float* src = (e < (size_t)MS * DD)
                         ? speech + e
                         : text + (e - (size_t)MS * DD);
        float4 x0 = *(const float4*)src;
        float4 x1 = *(const float4*)(src + 4);
        float xs[8] = {x0.x, x0.y, x0.z, x0.w, x1.x, x1.y, x1.z, x1.w};
        union { __half h[8]; uint4 v; } uh;
#pragma unroll
        for (int i = 0; i < 8; i++) uh.h[i] = __float2half_rn(xs[i]);
        *(uint4*)(g_Ah + e) = uh.v;
    } else {
        size_t w = e - (size_t)MA * DD;
        const float* src = Wm + w;
        float4 x0 = *(const float4*)src;
        float4 x1 = *(const float4*)(src + 4);
        float xs[8] = {x0.x, x0.y, x0.z, x0.w, x1.x, x1.y, x1.z, x1.w};
        union { __half h[8]; uint4 v; } uhi, ulo;
#pragma unroll
        for (int i = 0; i < 8; i++) {
            float xw = xs[i] * WSCALE;
            __half h = __float2half_rn(xw);
            uhi.h[i] = h;
            ulo.h[i] = __float2half_rn(xw - __half2float(h));
        }
        *(uint4*)(g_Wh + w) = uhi.v;
        *(uint4*)(g_Wl + w) = ulo.v;
    }

    if (blockIdx.x == 0) {
        const int i = threadIdx.x;
        if (i < 32) g_sp_cnt[i] = 0u;
        if (i == 32) g_tp_cnt = 0u;
        if (i < 8) {
            size_t base = (size_t)BB * TT_ * UU * VV;
            if (i < 4) out[base + i] = (float)slen[i];
            else       out[base + i] = (float)tlen[i - 4];
        }
    }
}

// ---------------------------------------------------------------------------
// Kernel 1: persistent tensor-core 2-term fp16 GEMM (148 CTAs x <=3 tiles).
// C = (Ah*Wh + Ah*Wl) * 2^-9  (+bias for text).
// Tile priority: idx 0..63 text tiles (unlock tp first), then speech rb-major
// -> results unlock progressively for the PDL-overlapped add kernel.
// Per tile: 64x64, 256 threads (8 warps = 4m x 2n), 3-stage cp.async.
// Flags: after each tile, sp_cnt[rb]++ / tp_cnt++ (threadfence-protected).
// ---------------------------------------------------------------------------
__global__ __launch_bounds__(256)
void mma_gemm_kernel(const float* __restrict__ bias)
{
    cudaTriggerProgrammaticLaunchCompletion();   // let the add kernel launch now

    __shared__ __align__(16) unsigned char smem[3][15360];

    const int tid = threadIdx.x;
    const int ar = tid >> 2, ac = tid & 3;
    const int soff = ar * 80 + ac * 16;
    const int lane = tid & 31;
    const int wrp  = tid >> 5;
    const int wm   = wrp & 3;
    const int wn   = wrp >> 2;
    const int aRow  = wm * 16 + (lane & 15);
    const int aByte = ((lane >> 4) & 1) * 16;
    const int bRow4  = wn * 32 + ((lane >> 4) & 1) * 8 + (lane & 7);
    const int bByte4 = ((lane >> 3) & 1) * 16;

    for (int idx = blockIdx.x; idx < 320; idx += 148) {
        // priority order: text first, then speech rb-major
        const int t  = (idx < 64) ? (256 + idx) : (idx - 64);
        const int rb = t >> 3;
        const int v0 = (t & 7) * 64;
        const bool is_text = (rb >= 32);
        const int m0 = rb * 64;
        float* C = is_text ? g_tp + (size_t)(rb - 32) * 64 * VV
                           : g_sp + (size_t)rb * 64 * VV;

        const __half* pAh = g_Ah + (size_t)(m0 + ar) * DD + ac * 8;
        const __half* pWh = g_Wh + (size_t)(v0 + ar) * DD + ac * 8;
        const __half* pWl = g_Wl + (size_t)(v0 + ar) * DD + ac * 8;

        float acc[4][4];
#pragma unroll
        for (int j = 0; j < 4; j++)
#pragma unroll
            for (int i = 0; i < 4; i++) acc[j][i] = 0.f;

        auto issue = [&](int kc, int s) {
            unsigned char* nb = smem[s];
            const int ko = kc * 32;
            CP16(s2u(nb +         soff), pAh + ko);
            CP16(s2u(nb +  5120 + soff), pWh + ko);
            CP16(s2u(nb + 10240 + soff), pWl + ko);
            CP_COMMIT();
        };

        issue(0, 0);
        issue(1, 1);

        int sbuf = 0;
        for (int kc = 0; kc < 16; kc++) {
            if (kc == 15) { CP_WAIT0(); } else { CP_WAIT1(); }
            __syncthreads();

            if (kc < 14) {
                int ns = sbuf + 2; if (ns >= 3) ns -= 3;
                issue(kc + 2, ns);
            }

            unsigned char* cb = smem[sbuf];
#pragma unroll
            for (int ks = 0; ks < 2; ks++) {
                uint32_t aAddr = s2u(cb + aRow * 80 + ks * 32 + aByte);
                uint32_t a0, a1, a2, a3;
                LDSM4(a0, a1, a2, a3, aAddr);

                uint32_t bAddrBase = s2u(cb + 5120 + bRow4 * 80 + ks * 32 + bByte4);
                uint32_t bh[8], bl[8];
#pragma unroll
                for (int jp = 0; jp < 2; jp++) {
                    uint32_t ba = bAddrBase + jp * (16 * 80);
                    LDSM4(bh[jp*4+0], bh[jp*4+1], bh[jp*4+2], bh[jp*4+3], ba);
                    LDSM4(bl[jp*4+0], bl[jp*4+1], bl[jp*4+2], bl[jp*4+3], ba + 5120);
                }
#pragma unroll
                for (int j = 0; j < 4; j++) {
                    MMA16816F16(acc[j], a0, a1, a2, a3, bh[j*2], bh[j*2+1]);
                    MMA16816F16(acc[j], a0, a1, a2, a3, bl[j*2], bl[j*2+1]);
                }
            }
            __syncthreads();
            if (++sbuf == 3) sbuf = 0;
        }

        const int erow  = wm * 16 + (lane >> 2);
        const int ecol0 = wn * 32 + (lane & 3) * 2;
#pragma unroll
        for (int j = 0; j < 4; j++) {
            const int col = ecol0 + j * 8;
            float b0v = 0.f, b1v = 0.f;
            if (is_text) { b0v = bias[v0 + col]; b1v = bias[v0 + col + 1]; }
            float2 o0 = make_float2(acc[j][0] * WINV + b0v, acc[j][1] * WINV + b1v);
            float2 o1 = make_float2(acc[j][2] * WINV + b0v, acc[j][3] * WINV + b1v);
            *(float2*)(C + (size_t)erow * VV + v0 + col)       = o0;
            *(float2*)(C + (size_t)(erow + 8) * VV + v0 + col) = o1;
        }

        // Publish tile completion
        __threadfence();
        __syncthreads();
        if (tid == 0) {
            if (is_text) atomicAdd(&g_tp_cnt, 1u);
            else         atomicAdd(&g_sp_cnt[rb], 1u);
        }
        __syncthreads();
    }
}

// ---------------------------------------------------------------------------
// Kernel 2: broadcast add (launched with PDL; overlaps with the GEMM).
// out[bt, u, v] = sp[bt, v] + tp[b*U + u, v].
// One block per bt row, 128 threads, plain stores (proven 87.5 us floor).
// Gated on sp_cnt[bt>>6]==8 and tp_cnt==64 via light spin.
// ---------------------------------------------------------------------------
__global__ __launch_bounds__(128)
void bcast_add_kernel(float* __restrict__ out)
{
    const int bt  = blockIdx.x;           // 0..2047
    const int rb  = bt >> 6;              // speech row-block
    const int b   = bt >> 9;              // batch index
    const int tid = threadIdx.x;          // 0..127 -> v4 index

    if (tid == 0) {
        while (*(volatile unsigned int*)&g_tp_cnt < 64u)      __nanosleep(64);
        while (*(volatile unsigned int*)&g_sp_cnt[rb] < 8u)   __nanosleep(64);
        __threadfence();
    }
    __syncthreads();

    const float4* sp4 = (const float4*)g_sp;
    const float4* tp4 = (const float4*)g_tp;

    float4 s = sp4[(size_t)bt * 128 + tid];

    const float4* tprow = tp4 + (size_t)b * UU * 128 + tid;
    float4* ob = (float4*)out + (size_t)bt * UU * 128 + tid;

#pragma unroll 4
    for (int u = 0; u < UU; u++) {
        float4 t = tprow[(size_t)u * 128];
        float4 r;
        r.x = s.x + t.x;
        r.y = s.y + t.y;
        r.z = s.z + t.z;
        r.w = s.w + t.w;
        ob[(size_t)u * 128] = r;
    }
}

extern "C" void kernel_launch(void* const* d_in, const int* in_sizes, int n_in,
                              void* d_out, int out_size)
{
    const float* speech = (const float*)d_in[0];
    const float* text   = (const float*)d_in[1];
    const float* Wm     = (const float*)d_in[2];
    const float* bias   = (const float*)d_in[3];
    const int*   slen   = (const int*)d_in[4];
    const int*   tlen   = (const int*)d_in[5];

    // Phase 0: fp16 conversion + counter reset + length tail
    convert_kernel<<<768, 256>>>(speech, text, Wm, slen, tlen, (float*)d_out);

    // Phase 1: persistent GEMM (triggers programmatic completion at entry)
    mma_gemm_kernel<<<148, 256>>>(bias);

    // Phase 2: broadcast add, PDL-overlapped with the GEMM, flag-gated.
    cudaLaunchConfig_t cfg = {};
    cfg.gridDim  = dim3(MS);
    cfg.blockDim = dim3(128);
    cfg.dynamicSmemBytes = 0;
    cfg.stream = 0;
    cudaLaunchAttribute attrs[1];
    attrs[0].id = cudaLaunchAttributeProgrammaticStreamSerialization;
    attrs[0].val.programmaticStreamSerializationAllowed = 1;
    cfg.attrs = attrs;
    cfg.numAttrs = 1;
    cudaLaunchKernelEx(&cfg, bcast_add_kernel, (float*)d_out);
}